// round 4
// baseline (speedup 1.0000x reference)
#include <cuda_runtime.h>
#include <cstdint>
#include <cstddef>

// LocalConvolution via warp-level bf16 split MMA (mma.sync m16n8k16), 2-stage
// software pipeline with double-buffered smem.
// out[b,o,i,j] = sum_k x_patch[b,k] * w[i,j,o,k], K = 1600 (c,u,v)
// Per CTA (pos=i*28+j): D[o=128, b=64] = W[128,K] @ P[64,K]^T

#define B_  64
#define C_  64
#define H_  32
#define W_  32
#define CC  28
#define O_  128
#define K_  1600
#define KT  64
#define NTILES 25
#define NPOS 784

// per-buffer smem layout: bf16 tiles, 144B padded rows (conflict-free ldsm)
#define ROWB 144
#define WHI_OFF 0
#define WLO_OFF (128*ROWB)               // 18432
#define PHI_OFF (2*128*ROWB)             // 36864
#define PLO_OFF (2*128*ROWB + 64*ROWB)   // 46080
#define BUFSZ   (2*128*ROWB + 2*64*ROWB) // 55296
#define SMEM_TOTAL (2*BUFSZ)             // 110592

__device__ __forceinline__ uint32_t smem_u32(const void* p) {
    uint32_t a;
    asm("{ .reg .u64 t; cvta.to.shared.u64 t, %1; cvt.u32.u64 %0, t; }" : "=r"(a) : "l"(p));
    return a;
}

// pack: low half = bf16(flo), high half = bf16(fhi)
__device__ __forceinline__ uint32_t cvt2(float flo, float fhi) {
    uint32_t r;
    asm("cvt.rn.bf16x2.f32 %0, %1, %2;" : "=r"(r) : "f"(fhi), "f"(flo));
    return r;
}

__device__ __forceinline__ void ldsm4(uint32_t* r, uint32_t addr) {
    asm volatile("ldmatrix.sync.aligned.m8n8.x4.shared.b16 {%0,%1,%2,%3}, [%4];"
                 : "=r"(r[0]), "=r"(r[1]), "=r"(r[2]), "=r"(r[3]) : "r"(addr));
}

__device__ __forceinline__ void mma16816(float* d, const uint32_t* a, uint32_t b0, uint32_t b1) {
    asm volatile(
        "mma.sync.aligned.m16n8k16.row.col.f32.bf16.bf16.f32 "
        "{%0,%1,%2,%3}, {%4,%5,%6,%7}, {%8,%9}, {%0,%1,%2,%3};"
        : "+f"(d[0]), "+f"(d[1]), "+f"(d[2]), "+f"(d[3])
        : "r"(a[0]), "r"(a[1]), "r"(a[2]), "r"(a[3]), "r"(b0), "r"(b1));
}

__global__ __launch_bounds__(256, 2)
void lc_hmma_kernel(const float* __restrict__ x,
                    const float* __restrict__ w,
                    float* __restrict__ out) {
    extern __shared__ char smem[];
    const uint32_t sbase = smem_u32(smem);

    const int tid = threadIdx.x;
    const int wid = tid >> 5;
    const int l   = tid & 31;

    const int pos = blockIdx.x;
    const int i = pos / CC;
    const int j = pos - i * CC;
    const float* __restrict__ wbase = w + (size_t)pos * (O_ * K_);

    // warp tile: 32(o) x 32(b)
    const int o0 = (wid >> 1) * 32;
    const int b0 = (wid & 1) * 32;

    // loader mapping for P: kq = tid&15 (k chunk of 4), bq = tid>>4 (4 b rows)
    const int kq = tid & 15;
    const int bq = tid >> 4;

    // ldmatrix lane base addresses (relative to buffer base)
    const uint32_t aRowRel = (uint32_t)((o0 + (l & 15)) * ROWB + (l >> 4) * 16);
    const uint32_t bRowRel = (uint32_t)(PHI_OFF + (b0 + (l & 7) + ((l >> 4) * 8)) * ROWB
                                        + ((l >> 3) & 1) * 16);

    float acc[2][4][4];
    #pragma unroll
    for (int mi = 0; mi < 2; mi++)
        #pragma unroll
        for (int bt = 0; bt < 4; bt++)
            #pragma unroll
            for (int c = 0; c < 4; c++) acc[mi][bt][c] = 0.0f;

    float4 wreg[8];
    float  preg[4][4];

    // ---- tile loaders (into registers) ----
    auto load_w = [&](int t) {
        const float* wt = wbase + t * KT;
        #pragma unroll
        for (int ci = 0; ci < 8; ci++) {
            int ch = tid + ci * 256;
            int o = ch >> 4, kc = ch & 15;
            wreg[ci] = *(const float4*)(wt + (size_t)o * K_ + kc * 4);
        }
    };
    auto load_p = [&](int t) {
        int xoff[4];
        #pragma unroll
        for (int e = 0; e < 4; e++) {
            int k = t * KT + kq * 4 + e;
            int c = k / 25;
            int rem = k - c * 25;
            int u = rem / 5;
            int v = rem - u * 5;
            xoff[e] = (c * H_ + (i + u)) * W_ + (j + v);
        }
        #pragma unroll
        for (int bi = 0; bi < 4; bi++) {
            const float* xb = x + (size_t)(bq * 4 + bi) * (C_ * H_ * W_);
            #pragma unroll
            for (int e = 0; e < 4; e++) preg[bi][e] = __ldg(xb + xoff[e]);
        }
    };

    // ---- convert regs -> smem buffer (hi/lo split) ----
    auto cvt_sts = [&](uint32_t bufOff) {
        #pragma unroll
        for (int ci = 0; ci < 8; ci++) {
            int ch = tid + ci * 256;
            int o = ch >> 4, kc = ch & 15;
            float4 f = wreg[ci];
            uint32_t h01 = cvt2(f.x, f.y);
            uint32_t h23 = cvt2(f.z, f.w);
            float lo0 = f.x - __uint_as_float(h01 << 16);
            float lo1 = f.y - __uint_as_float(h01 & 0xffff0000u);
            float lo2 = f.z - __uint_as_float(h23 << 16);
            float lo3 = f.w - __uint_as_float(h23 & 0xffff0000u);
            uint32_t l01 = cvt2(lo0, lo1);
            uint32_t l23 = cvt2(lo2, lo3);
            uint32_t off = bufOff + (uint32_t)o * ROWB + (uint32_t)kc * 8;
            *(uint2*)(smem + WHI_OFF + off) = make_uint2(h01, h23);
            *(uint2*)(smem + WLO_OFF + off) = make_uint2(l01, l23);
        }
        #pragma unroll
        for (int bi = 0; bi < 4; bi++) {
            float f0 = preg[bi][0], f1 = preg[bi][1], f2 = preg[bi][2], f3 = preg[bi][3];
            uint32_t h01 = cvt2(f0, f1);
            uint32_t h23 = cvt2(f2, f3);
            float lo0 = f0 - __uint_as_float(h01 << 16);
            float lo1 = f1 - __uint_as_float(h01 & 0xffff0000u);
            float lo2 = f2 - __uint_as_float(h23 << 16);
            float lo3 = f3 - __uint_as_float(h23 & 0xffff0000u);
            uint32_t l01 = cvt2(lo0, lo1);
            uint32_t l23 = cvt2(lo2, lo3);
            uint32_t off = bufOff + (uint32_t)(bq * 4 + bi) * ROWB + (uint32_t)kq * 8;
            *(uint2*)(smem + PHI_OFF + off) = make_uint2(h01, h23);
            *(uint2*)(smem + PLO_OFF + off) = make_uint2(l01, l23);
        }
    };

    // ---- prologue: fill buf0 with tile0, regs with tile1 ----
    load_w(0); load_p(0);
    cvt_sts(0);
    load_w(1); load_p(1);
    __syncthreads();

    #pragma unroll 1
    for (int t = 0; t < NTILES; t++) {
        const uint32_t bufOff  = (uint32_t)(t & 1) * BUFSZ;
        const uint32_t bufOffN = (uint32_t)((t + 1) & 1) * BUFSZ;

        // stage tile t+1 (from regs) into the other buffer, then prefetch t+2
        if (t + 1 < NTILES) {
            cvt_sts(bufOffN);
            if (t + 2 < NTILES) { load_w(t + 2); load_p(t + 2); }
        }

        // ---- MMA on buf(t): 4 k-steps of 16, 3 split combos ----
        const uint32_t aRow = sbase + bufOff + aRowRel;
        const uint32_t bRow = sbase + bufOff + bRowRel;
        #pragma unroll
        for (int ks = 0; ks < 4; ks++) {
            const uint32_t colb = (uint32_t)ks * 32;
            uint32_t ah[2][4], al[2][4], bh[2][4], bl[2][4];
            ldsm4(ah[0], aRow + colb);
            ldsm4(ah[1], aRow + colb + 16 * ROWB);
            ldsm4(al[0], aRow + colb + (WLO_OFF - WHI_OFF));
            ldsm4(al[1], aRow + colb + (WLO_OFF - WHI_OFF) + 16 * ROWB);
            ldsm4(bh[0], bRow + colb);
            ldsm4(bh[1], bRow + colb + 16 * ROWB);
            ldsm4(bl[0], bRow + colb + (PLO_OFF - PHI_OFF));
            ldsm4(bl[1], bRow + colb + (PLO_OFF - PHI_OFF) + 16 * ROWB);
            #pragma unroll
            for (int mi = 0; mi < 2; mi++) {
                #pragma unroll
                for (int bt = 0; bt < 4; bt++) {
                    const int g = bt >> 1, p = (bt & 1) * 2;
                    mma16816(acc[mi][bt], ah[mi], bh[g][p], bh[g][p + 1]);
                    mma16816(acc[mi][bt], ah[mi], bl[g][p], bl[g][p + 1]);
                    mma16816(acc[mi][bt], al[mi], bh[g][p], bh[g][p + 1]);
                }
            }
        }
        // one barrier per tile: MMA(t) done before anyone overwrites buf(t)
        // at the next iteration's cvt_sts; STS(t+1) done before its LDSMs.
        __syncthreads();
    }

    // ---- epilogue ----
    const int orow = l >> 2;
    const int bcol = (l & 3) * 2;
    #pragma unroll
    for (int mi = 0; mi < 2; mi++) {
        #pragma unroll
        for (int bt = 0; bt < 4; bt++) {
            #pragma unroll
            for (int c = 0; c < 4; c++) {
                int o = o0 + mi * 16 + orow + (c >> 1) * 8;
                int b = b0 + bt * 8 + bcol + (c & 1);
                out[((size_t)b * O_ + o) * NPOS + pos] = acc[mi][bt][c];
            }
        }
    }
}

extern "C" void kernel_launch(void* const* d_in, const int* in_sizes, int n_in,
                              void* d_out, int out_size) {
    const float* x;
    const float* w;
    if (in_sizes[0] == B_ * C_ * H_ * W_) {
        x = (const float*)d_in[0];
        w = (const float*)d_in[1];
    } else {
        x = (const float*)d_in[1];
        w = (const float*)d_in[0];
    }
    float* out = (float*)d_out;
    cudaFuncSetAttribute(lc_hmma_kernel, cudaFuncAttributeMaxDynamicSharedMemorySize, SMEM_TOTAL);
    lc_hmma_kernel<<<NPOS, 256, SMEM_TOTAL>>>(x, w, out);
}

// round 6
// speedup vs baseline: 3.0305x; 3.0305x over previous
#include <cuda_runtime.h>
#include <cstdint>
#include <cstddef>

// LocalConvolution via warp-level bf16 split MMA (mma.sync m16n8k16).
// Prep kernel pre-splits x into bf16 hi/lo, transposed to [c,h,w][b] so the
// main kernel's P tiles are dense vector loads with no conversion.
// Main (per CTA = one position): D[o=128, b=64] = W[128,K] @ P[64,K]^T, K=1600.

#define B_  64
#define C_  64
#define H_  32
#define W_  32
#define CC  28
#define O_  128
#define K_  1600
#define KT  64
#define NTILES 25
#define NPOS 784
#define CHW (C_*H_*W_)        // 65536

// main-kernel smem: bf16 tiles, 144B padded rows (conflict-free ldsm phases)
#define ROWB 144
#define WHI_OFF 0
#define WLO_OFF (128*ROWB)                 // 18432
#define PHI_OFF (2*128*ROWB)               // 36864  (P: 64 k-rows x 144B)
#define PLO_OFF (2*128*ROWB + 64*ROWB)     // 46080
#define SMEM_TOTAL (2*128*ROWB + 2*64*ROWB)  // 55296

// pre-split x: [chw][b] bf16, 16B-aligned via uint4 arrays (8 MB each)
__device__ uint4 g_xhi[CHW * B_ * 2 / 16];
__device__ uint4 g_xlo[CHW * B_ * 2 / 16];

__device__ __forceinline__ uint32_t smem_u32(const void* p) {
    uint32_t a;
    asm("{ .reg .u64 t; cvta.to.shared.u64 t, %1; cvt.u32.u64 %0, t; }" : "=r"(a) : "l"(p));
    return a;
}

// pack: low half = bf16(flo), high half = bf16(fhi)
__device__ __forceinline__ uint32_t cvt2(float flo, float fhi) {
    uint32_t r;
    asm("cvt.rn.bf16x2.f32 %0, %1, %2;" : "=r"(r) : "f"(fhi), "f"(flo));
    return r;
}

__device__ __forceinline__ void ldsm4(uint32_t* r, uint32_t addr) {
    asm volatile("ldmatrix.sync.aligned.m8n8.x4.shared.b16 {%0,%1,%2,%3}, [%4];"
                 : "=r"(r[0]), "=r"(r[1]), "=r"(r[2]), "=r"(r[3]) : "r"(addr));
}

__device__ __forceinline__ void ldsm4t(uint32_t* r, uint32_t addr) {
    asm volatile("ldmatrix.sync.aligned.m8n8.x4.trans.shared.b16 {%0,%1,%2,%3}, [%4];"
                 : "=r"(r[0]), "=r"(r[1]), "=r"(r[2]), "=r"(r[3]) : "r"(addr));
}

__device__ __forceinline__ void mma16816(float* d, const uint32_t* a, uint32_t b0, uint32_t b1) {
    asm volatile(
        "mma.sync.aligned.m16n8k16.row.col.f32.bf16.bf16.f32 "
        "{%0,%1,%2,%3}, {%4,%5,%6,%7}, {%8,%9}, {%0,%1,%2,%3};"
        : "+f"(d[0]), "+f"(d[1]), "+f"(d[2]), "+f"(d[3])
        : "r"(a[0]), "r"(a[1]), "r"(a[2]), "r"(a[3]), "r"(b0), "r"(b1));
}

// ---- prep: x[b][chw] f32 -> g_xhi/g_xlo [chw][b] bf16 (hi/lo RN split) ----
// block = 256 threads handles 64 consecutive chw for all 64 b.
__global__ __launch_bounds__(256)
void prep_kernel(const float* __restrict__ x) {
    __shared__ float ts[B_][65];
    const int tid = threadIdx.x;
    const int wid = tid >> 5;
    const int lane = tid & 31;
    const int chw0 = blockIdx.x * 64;

    // load: warp w covers b = w*8 .. w*8+7, 64 chw each (coalesced)
    #pragma unroll
    for (int bi = 0; bi < 8; bi++) {
        int b = wid * 8 + bi;
        const float* xp = x + (size_t)b * CHW + chw0;
        ts[b][lane]      = xp[lane];
        ts[b][lane + 32] = xp[lane + 32];
    }
    __syncthreads();

    // store: thread handles (chw_l = tid>>2, b-chunk of 16 = tid&3)
    const int chw_l = tid >> 2;
    const int bc = tid & 3;
    uint32_t hi[8], lo[8];
    #pragma unroll
    for (int p = 0; p < 8; p++) {
        float f0 = ts[bc * 16 + p * 2][chw_l];
        float f1 = ts[bc * 16 + p * 2 + 1][chw_l];
        uint32_t h = cvt2(f0, f1);
        float l0 = f0 - __uint_as_float(h << 16);
        float l1 = f1 - __uint_as_float(h & 0xffff0000u);
        hi[p] = h;
        lo[p] = cvt2(l0, l1);
    }
    char* oh = (char*)g_xhi + (size_t)(chw0 + chw_l) * 128 + bc * 32;
    char* ol = (char*)g_xlo + (size_t)(chw0 + chw_l) * 128 + bc * 32;
    *(uint4*)oh        = make_uint4(hi[0], hi[1], hi[2], hi[3]);
    *(uint4*)(oh + 16) = make_uint4(hi[4], hi[5], hi[6], hi[7]);
    *(uint4*)ol        = make_uint4(lo[0], lo[1], lo[2], lo[3]);
    *(uint4*)(ol + 16) = make_uint4(lo[4], lo[5], lo[6], lo[7]);
}

// ---- main kernel ----
__global__ __launch_bounds__(256, 2)
void lc_hmma_kernel(const float* __restrict__ x,
                    const float* __restrict__ w,
                    float* __restrict__ out) {
    extern __shared__ char smem[];
    const uint32_t sbase = smem_u32(smem);

    const int tid = threadIdx.x;
    const int wid = tid >> 5;
    const int l   = tid & 31;

    const int pos = blockIdx.x;
    const int i = pos / CC;
    const int j = pos - i * CC;
    const float* __restrict__ wbase = w + (size_t)pos * (O_ * K_);

    // warp tile: 32(o) x 32(b)
    const int o0 = (wid >> 1) * 32;
    const int b0 = (wid & 1) * 32;

    // P loader mapping: kr = tid>>2 (k row in tile), c2 = tid&3 (32B chunk)
    const int kr = tid >> 2;
    const int c2 = tid & 3;

    // ldmatrix lane addresses
    // A (W, [o][k] rows): lanes 0-15 rows o, (l>>4) selects k-halves along row
    const uint32_t aRow = sbase + WHI_OFF
                        + (uint32_t)((o0 + (l & 15)) * ROWB + (l >> 4) * 16);
    // B (P, [k][b] rows, .trans): row = ((l>>3)&1)*8 + (l&7), col byte = (b0 + (l>>4)*8)*2
    const uint32_t bRow = sbase + PHI_OFF
                        + (uint32_t)((((l >> 3) & 1) * 8 + (l & 7)) * ROWB
                                     + (b0 + (l >> 4) * 8) * 2);

    float acc[2][4][4];
    #pragma unroll
    for (int mi = 0; mi < 2; mi++)
        #pragma unroll
        for (int bt = 0; bt < 4; bt++)
            #pragma unroll
            for (int c = 0; c < 4; c++) acc[mi][bt][c] = 0.0f;

    float4 wreg[8];
    auto load_w = [&](int t) {
        const float* wt = wbase + t * KT;
        #pragma unroll
        for (int ci = 0; ci < 8; ci++) {
            int ch = tid + ci * 256;
            int o = ch >> 4, kc = ch & 15;
            wreg[ci] = *(const float4*)(wt + (size_t)o * K_ + kc * 4);
        }
    };

    // ---- prologue ----
    load_w(0);

    #pragma unroll 1
    for (int t = 0; t < NTILES; t++) {
        // ---- P loads (dense bf16, hi+lo): 4 x LDG.128 ----
        int kg = t * KT + kr;
        int c = kg / 25;
        int rem = kg - c * 25;
        int u = rem / 5;
        int v = rem - u * 5;
        size_t chw = (size_t)(c * (H_ * W_) + (i + u) * W_ + (j + v));
        const char* ph = (const char*)g_xhi + chw * 128 + c2 * 32;
        const char* pl = (const char*)g_xlo + chw * 128 + c2 * 32;
        uint4 ph0 = *(const uint4*)ph;
        uint4 ph1 = *(const uint4*)(ph + 16);
        uint4 pl0 = *(const uint4*)pl;
        uint4 pl1 = *(const uint4*)(pl + 16);

        // ---- W convert + STS (covers P load latency) ----
        #pragma unroll
        for (int ci = 0; ci < 8; ci++) {
            int ch = tid + ci * 256;
            int o = ch >> 4, kc = ch & 15;
            float4 f = wreg[ci];
            uint32_t h01 = cvt2(f.x, f.y);
            uint32_t h23 = cvt2(f.z, f.w);
            float lo0 = f.x - __uint_as_float(h01 << 16);
            float lo1 = f.y - __uint_as_float(h01 & 0xffff0000u);
            float lo2 = f.z - __uint_as_float(h23 << 16);
            float lo3 = f.w - __uint_as_float(h23 & 0xffff0000u);
            uint32_t l01 = cvt2(lo0, lo1);
            uint32_t l23 = cvt2(lo2, lo3);
            uint32_t off = (uint32_t)o * ROWB + (uint32_t)kc * 8;
            *(uint2*)(smem + WHI_OFF + off) = make_uint2(h01, h23);
            *(uint2*)(smem + WLO_OFF + off) = make_uint2(l01, l23);
        }

        // ---- P STS (direct) ----
        {
            char* dh = smem + PHI_OFF + kr * ROWB + c2 * 32;
            char* dl = smem + PLO_OFF + kr * ROWB + c2 * 32;
            *(uint4*)dh        = ph0;
            *(uint4*)(dh + 16) = ph1;
            *(uint4*)dl        = pl0;
            *(uint4*)(dl + 16) = pl1;
        }
        __syncthreads();

        // ---- prefetch next W tile (covered by MMA block) ----
        if (t + 1 < NTILES) load_w(t + 1);

        // ---- MMA: 4 k-steps of 16, 3 split combos ----
        #pragma unroll
        for (int ks = 0; ks < 4; ks++) {
            const uint32_t aCol = (uint32_t)ks * 32;        // A: +32B along row
            const uint32_t bOff = (uint32_t)ks * 16 * ROWB; // B: +16 k-rows
            uint32_t ah[2][4], al[2][4], bh[2][4], bl[2][4];
            ldsm4(ah[0], aRow + aCol);
            ldsm4(ah[1], aRow + aCol + 16 * ROWB);
            ldsm4(al[0], aRow + aCol + (WLO_OFF - WHI_OFF));
            ldsm4(al[1], aRow + aCol + (WLO_OFF - WHI_OFF) + 16 * ROWB);
            ldsm4t(bh[0], bRow + bOff);
            ldsm4t(bh[1], bRow + bOff + 16 * 2);            // n-octets +16 b -> +32B
            ldsm4t(bl[0], bRow + bOff + (PLO_OFF - PHI_OFF));
            ldsm4t(bl[1], bRow + bOff + (PLO_OFF - PHI_OFF) + 16 * 2);
            #pragma unroll
            for (int mi = 0; mi < 2; mi++) {
                #pragma unroll
                for (int bt = 0; bt < 4; bt++) {
                    const int g = bt >> 1, p = (bt & 1) * 2;
                    mma16816(acc[mi][bt], ah[mi], bh[g][p], bh[g][p + 1]);
                    mma16816(acc[mi][bt], ah[mi], bl[g][p], bl[g][p + 1]);
                    mma16816(acc[mi][bt], al[mi], bh[g][p], bh[g][p + 1]);
                }
            }
        }
        __syncthreads();
    }

    // ---- epilogue: o = o0+mi*16+(l>>2)+8*(c>>1), b = b0+bt*8+(l&3)*2+(c&1)
    const int orow = l >> 2;
    const int bcol = (l & 3) * 2;
    #pragma unroll
    for (int mi = 0; mi < 2; mi++) {
        #pragma unroll
        for (int bt = 0; bt < 4; bt++) {
            #pragma unroll
            for (int c = 0; c < 4; c++) {
                int o = o0 + mi * 16 + orow + (c >> 1) * 8;
                int b = b0 + bt * 8 + bcol + (c & 1);
                out[((size_t)b * O_ + o) * NPOS + pos] = acc[mi][bt][c];
            }
        }
    }
}

extern "C" void kernel_launch(void* const* d_in, const int* in_sizes, int n_in,
                              void* d_out, int out_size) {
    const float* x;
    const float* w;
    if (in_sizes[0] == B_ * C_ * H_ * W_) {
        x = (const float*)d_in[0];
        w = (const float*)d_in[1];
    } else {
        x = (const float*)d_in[1];
        w = (const float*)d_in[0];
    }
    float* out = (float*)d_out;
    prep_kernel<<<CHW / 64, 256>>>(x);
    cudaFuncSetAttribute(lc_hmma_kernel, cudaFuncAttributeMaxDynamicSharedMemorySize, SMEM_TOTAL);
    lc_hmma_kernel<<<NPOS, 256, SMEM_TOTAL>>>(x, w, out);
}